// round 7
// baseline (speedup 1.0000x reference)
#include <cuda_runtime.h>
#include <cuda_bf16.h>
#include <cstdint>

// ============================================================================
// MixResidualBlockC via warp-level bf16 mma.sync (3-split fp32 emulation).
//   stage1: h1 = sincos(W1[256,256] @ xt)           (pixel-major bf16 hi/lo)
//   stage2: h2 = sincos(W2[256,512] @ h1)
//   stage3: out = W3[256,768] @ [h2 ; xt] + b3      (W3 = [k_out | k_short])
// R7: CTA 128px x 256ch (full N), warp tile 64x64, BK=64.
// LDSM wavefronts per MMA: 2.0 -> 0.67 (L1tex was co-binding with tensor).
// ============================================================================

#define NPIX 4096
#define NB 16
#define STRIDE 144                     // bytes per 64-bf16 smem row (padded)
#define APLANE (128 * STRIDE)          // 18432
#define BPLANE (256 * STRIDE)          // 36864
#define OFF_AH 0
#define OFF_AL APLANE
#define OFF_BH (2 * APLANE)
#define OFF_BL (2 * APLANE + BPLANE)
#define BUFSZ (2 * APLANE + 2 * BPLANE)  // 110592
#define SMEM_DYN (2 * BUFSZ)             // 221184

// -------------------- device scratch --------------------------------------
__device__ float g_mix[NB * 8];
__device__ float g_b1[NB * 256], g_b2[NB * 256], g_b3[NB * 256];
__device__ __nv_bfloat16 g_w1h[NB * 256 * 256], g_w1l[NB * 256 * 256];
__device__ __nv_bfloat16 g_w2h[NB * 256 * 512], g_w2l[NB * 256 * 512];
__device__ __nv_bfloat16 g_w3h[NB * 256 * 768], g_w3l[NB * 256 * 768];
__device__ __nv_bfloat16 g_xth[(size_t)NB * NPIX * 256], g_xtl[(size_t)NB * NPIX * 256];
__device__ __nv_bfloat16 g_h1h[(size_t)NB * NPIX * 512], g_h1l[(size_t)NB * NPIX * 512];
__device__ __nv_bfloat16 g_h2h[(size_t)NB * NPIX * 512], g_h2l[(size_t)NB * NPIX * 512];

// -------------------- PTX helpers (all arch-portable) ----------------------
__device__ __forceinline__ uint32_t smem_u32(const void* p) {
    uint32_t a;
    asm("{ .reg .u64 t; cvta.to.shared.u64 t, %1; cvt.u32.u64 %0, t; }" : "=r"(a) : "l"(p));
    return a;
}
__device__ __forceinline__ void cpa16(uint32_t dst, const void* src) {
    asm volatile("cp.async.cg.shared.global [%0], [%1], 16;" :: "r"(dst), "l"(src));
}
__device__ __forceinline__ void cpa_commit() { asm volatile("cp.async.commit_group;"); }

__device__ __forceinline__ void ldsm_x4(uint32_t* r, uint32_t addr) {
    asm volatile("ldmatrix.sync.aligned.m8n8.x4.shared.b16 {%0,%1,%2,%3}, [%4];"
                 : "=r"(r[0]), "=r"(r[1]), "=r"(r[2]), "=r"(r[3]) : "r"(addr));
}
__device__ __forceinline__ void mma_bf16(float* d, const uint32_t* a,
                                         uint32_t b0, uint32_t b1) {
    asm volatile(
        "mma.sync.aligned.m16n8k16.row.col.f32.bf16.bf16.f32 "
        "{%0,%1,%2,%3}, {%4,%5,%6,%7}, {%8,%9}, {%0,%1,%2,%3};"
        : "+f"(d[0]), "+f"(d[1]), "+f"(d[2]), "+f"(d[3])
        : "r"(a[0]), "r"(a[1]), "r"(a[2]), "r"(a[3]), "r"(b0), "r"(b1));
}
__device__ __forceinline__ uint32_t packbf2(float a, float b) {
    __nv_bfloat16 h0 = __float2bfloat16(a), h1 = __float2bfloat16(b);
    return (uint32_t)__bfloat16_as_ushort(h0) | ((uint32_t)__bfloat16_as_ushort(h1) << 16);
}

// -------------------- K0: mixing coefficients ------------------------------
__global__ void mix_kernel(const float* __restrict__ lat, const float* __restrict__ wd,
                           const float* __restrict__ bd) {
    int t = threadIdx.x;
    if (t < 128) {
        int b = t >> 3, m = t & 7;
        float a = bd[m];
        const float* lp = lat + b * 512;
        const float* wp = wd + m * 512;
        #pragma unroll 8
        for (int l = 0; l < 512; l++) a += lp[l] * wp[l];
        g_mix[t] = a;
    }
}

// -------------------- K1: weight mixing + bf16 hi/lo split -----------------
__global__ void prep_kernel(const float* __restrict__ kin, const float* __restrict__ kmid,
                            const float* __restrict__ kout, const float* __restrict__ ksh,
                            const float* __restrict__ bin, const float* __restrict__ bmid,
                            const float* __restrict__ bout, const float* __restrict__ bsh) {
    __shared__ float smix[128];
    if (threadIdx.x < 128) smix[threadIdx.x] = g_mix[threadIdx.x];
    __syncthreads();
    int p = blockIdx.x * 256 + threadIdx.x;
    float v[8];

    if (p < 65536) {  // w1 (k_in)
        #pragma unroll
        for (int m = 0; m < 8; m++) v[m] = kin[m * 65536 + p];
        #pragma unroll
        for (int b = 0; b < NB; b++) {
            float a = 0.f;
            #pragma unroll
            for (int m = 0; m < 8; m++) a += smix[b * 8 + m] * v[m];
            __nv_bfloat16 h = __float2bfloat16(a);
            g_w1h[b * 65536 + p] = h;
            g_w1l[b * 65536 + p] = __float2bfloat16(a - __bfloat162float(h));
        }
    } else if (p < 196608) {  // w2 (k_mid)
        int q = p - 65536;
        #pragma unroll
        for (int m = 0; m < 8; m++) v[m] = kmid[m * 131072 + q];
        #pragma unroll
        for (int b = 0; b < NB; b++) {
            float a = 0.f;
            #pragma unroll
            for (int m = 0; m < 8; m++) a += smix[b * 8 + m] * v[m];
            __nv_bfloat16 h = __float2bfloat16(a);
            g_w2h[b * 131072 + q] = h;
            g_w2l[b * 131072 + q] = __float2bfloat16(a - __bfloat162float(h));
        }
    } else if (p < 327680) {  // w3 k_out part: cols [0,512)
        int q = p - 196608;
        int o = q >> 9, i = q & 511;
        #pragma unroll
        for (int m = 0; m < 8; m++) v[m] = kout[m * 131072 + q];
        int di = o * 768 + i;
        #pragma unroll
        for (int b = 0; b < NB; b++) {
            float a = 0.f;
            #pragma unroll
            for (int m = 0; m < 8; m++) a += smix[b * 8 + m] * v[m];
            __nv_bfloat16 h = __float2bfloat16(a);
            g_w3h[b * 196608 + di] = h;
            g_w3l[b * 196608 + di] = __float2bfloat16(a - __bfloat162float(h));
        }
    } else if (p < 393216) {  // w3 k_short part: cols [512,768)
        int q = p - 327680;
        int o = q >> 8, i = q & 255;
        #pragma unroll
        for (int m = 0; m < 8; m++) v[m] = ksh[m * 65536 + q];
        int di = o * 768 + 512 + i;
        #pragma unroll
        for (int b = 0; b < NB; b++) {
            float a = 0.f;
            #pragma unroll
            for (int m = 0; m < 8; m++) a += smix[b * 8 + m] * v[m];
            __nv_bfloat16 h = __float2bfloat16(a);
            g_w3h[b * 196608 + di] = h;
            g_w3l[b * 196608 + di] = __float2bfloat16(a - __bfloat162float(h));
        }
    } else if (p < 393472) {  // biases
        int r = p - 393216;
        float vi[8], vm[8], vo[8];
        #pragma unroll
        for (int m = 0; m < 8; m++) {
            vi[m] = bin[m * 256 + r];
            vm[m] = bmid[m * 256 + r];
            vo[m] = bout[m * 256 + r] + bsh[m * 256 + r];
        }
        #pragma unroll
        for (int b = 0; b < NB; b++) {
            float a1 = 0.f, a2 = 0.f, a3 = 0.f;
            #pragma unroll
            for (int m = 0; m < 8; m++) {
                float mx = smix[b * 8 + m];
                a1 += mx * vi[m]; a2 += mx * vm[m]; a3 += mx * vo[m];
            }
            g_b1[b * 256 + r] = a1;
            g_b2[b * 256 + r] = a2;
            g_b3[b * 256 + r] = a3;
        }
    }
}

// -------------------- K2: x transpose + split  x[b,c,p] -> xt[b,p,c] -------
__global__ void xt_kernel(const float* __restrict__ x) {
    __shared__ float ts[32][33];
    int b = blockIdx.z, p0 = blockIdx.x * 32, c0 = blockIdx.y * 32;
    const float* src = x + ((size_t)b * 256 + c0) * NPIX + p0;
    for (int r = threadIdx.y; r < 32; r += 8)
        ts[r][threadIdx.x] = src[(size_t)r * NPIX + threadIdx.x];
    __syncthreads();
    int lane = threadIdx.x;
    for (int pr = threadIdx.y; pr < 32; pr += 8) {
        float v = ts[lane][pr];
        __nv_bfloat16 h = __float2bfloat16(v);
        __nv_bfloat16 l = __float2bfloat16(v - __bfloat162float(h));
        size_t di = ((size_t)b * NPIX + p0 + pr) * 256 + c0 + lane;
        g_xth[di] = h;
        g_xtl[di] = l;
    }
}

// -------------------- GEMM stage (mma.sync bf16 3-split) -------------------
// CTA: 128 px x 256 ch, 8 warps (2 x 4), warp tile 64 px x 64 ch.
template <int MODE>  // 1,2,3
__global__ void __launch_bounds__(256, 1)
gemm_stage(float* __restrict__ out) {
    constexpr int K = (MODE == 1) ? 256 : (MODE == 2) ? 512 : 768;
    constexpr int NCH = K / 64;
    constexpr int AROW = (MODE == 1) ? 256 : 512;

    extern __shared__ __align__(16) char dsm[];
    const uint32_t sbase = smem_u32(dsm);
    __shared__ float sbias[256];

    const int tid = threadIdx.x;
    const int lane = tid & 31;
    const int wid = tid >> 5;
    const int warp_m = wid & 1;       // 0..1  (64 px each)
    const int warp_n = wid >> 1;      // 0..3  (64 ch each)
    const int b = blockIdx.y;
    const int p0 = blockIdx.x * 128;

    const __nv_bfloat16 *Ah, *Al, *Bh, *Bl;
    const float* bias;
    if constexpr (MODE == 1) {
        Ah = g_xth + (size_t)b * NPIX * 256; Al = g_xtl + (size_t)b * NPIX * 256;
        Bh = g_w1h + (size_t)b * 65536;      Bl = g_w1l + (size_t)b * 65536;
        bias = g_b1 + b * 256;
    } else if constexpr (MODE == 2) {
        Ah = g_h1h + (size_t)b * NPIX * 512; Al = g_h1l + (size_t)b * NPIX * 512;
        Bh = g_w2h + (size_t)b * 131072;     Bl = g_w2l + (size_t)b * 131072;
        bias = g_b2 + b * 256;
    } else {
        Ah = g_h2h + (size_t)b * NPIX * 512; Al = g_h2l + (size_t)b * NPIX * 512;
        Bh = g_w3h + (size_t)b * 196608;     Bl = g_w3l + (size_t)b * 196608;
        bias = g_b3 + b * 256;
    }
    const __nv_bfloat16* Xh = g_xth + (size_t)b * NPIX * 256;  // MODE3 tail
    const __nv_bfloat16* Xl = g_xtl + (size_t)b * NPIX * 256;

    sbias[tid] = bias[tid];

    // ---- chunk copier: A 2048 + B 4096 16B units ---------------------------
    auto copy_chunk = [&](int ch, int buf) {
        const int k0 = ch * 64;
        const uint32_t bb = sbase + buf * BUFSZ;
        const __nv_bfloat16 *pAh = Ah, *pAl = Al;
        int acol = k0, arow = AROW;
        if (MODE == 3 && k0 >= 512) { pAh = Xh; pAl = Xl; acol = k0 - 512; arow = 256; }
        #pragma unroll
        for (int j = 0; j < 8; j++) {   // A: 2 planes x 128 rows x 8 units
            int u = tid + j * 256;
            int plane = u >> 10, r = (u >> 3) & 127, c = u & 7;
            uint32_t dst = bb + plane * APLANE + r * STRIDE + c * 16;
            const __nv_bfloat16* src = (plane ? pAl : pAh) +
                                       (size_t)(p0 + r) * arow + acol + c * 8;
            cpa16(dst, src);
        }
        #pragma unroll
        for (int j = 0; j < 16; j++) {  // B: 2 planes x 256 rows x 8 units
            int u = tid + j * 256;
            int plane = u >> 11, r = (u >> 3) & 255, c = u & 7;
            uint32_t dst = bb + OFF_BH + plane * BPLANE + r * STRIDE + c * 16;
            const __nv_bfloat16* src = (plane ? Bl : Bh) + (size_t)r * K + k0 + c * 8;
            cpa16(dst, src);
        }
        cpa_commit();
    };

    // ---- ldmatrix lane address offsets ----
    const int a_row_off = (warp_m * 64 + (lane & 15)) * STRIDE + ((lane >> 4) & 1) * 16;
    const int b_row_off = (warp_n * 64 + (lane & 15)) * STRIDE + ((lane >> 4) & 1) * 16;

    float acc[4][8][4];
    #pragma unroll
    for (int i = 0; i < 4; i++)
        #pragma unroll
        for (int j = 0; j < 8; j++)
            #pragma unroll
            for (int q = 0; q < 4; q++) acc[i][j][q] = 0.f;

    copy_chunk(0, 0);
    if (NCH > 1) copy_chunk(1, 1);

    for (int it = 0; it < NCH; it++) {
        const int buf = it & 1;
        if (it + 1 < NCH) asm volatile("cp.async.wait_group 1;" ::: "memory");
        else              asm volatile("cp.async.wait_group 0;" ::: "memory");
        __syncthreads();
        const uint32_t bb = sbase + buf * BUFSZ;

        #pragma unroll
        for (int ks = 0; ks < 4; ks++) {
            // ---- phase 1: Ah x Bh (32 MMAs / 32 wf) ----
            uint32_t fAh[4][4], fBh[4][4];
            #pragma unroll
            for (int mi = 0; mi < 4; mi++)
                ldsm_x4(fAh[mi], bb + OFF_AH + a_row_off + mi * (16 * STRIDE) + ks * 32);
            #pragma unroll
            for (int np = 0; np < 4; np++)
                ldsm_x4(fBh[np], bb + OFF_BH + b_row_off + np * (16 * STRIDE) + ks * 32);
            #pragma unroll
            for (int mi = 0; mi < 4; mi++)
                #pragma unroll
                for (int np = 0; np < 4; np++) {
                    mma_bf16(acc[mi][np * 2 + 0], fAh[mi], fBh[np][0], fBh[np][2]);
                    mma_bf16(acc[mi][np * 2 + 1], fAh[mi], fBh[np][1], fBh[np][3]);
                }

            // ---- phase 2: Al x Bh (Bh dies after this) ----
            uint32_t fAl[4][4];
            #pragma unroll
            for (int mi = 0; mi < 4; mi++)
                ldsm_x4(fAl[mi], bb + OFF_AL + a_row_off + mi * (16 * STRIDE) + ks * 32);
            #pragma unroll
            for (int mi = 0; mi < 4; mi++)
                #pragma unroll
                for (int np = 0; np < 4; np++) {
                    mma_bf16(acc[mi][np * 2 + 0], fAl[mi], fBh[np][0], fBh[np][2]);
                    mma_bf16(acc[mi][np * 2 + 1], fAl[mi], fBh[np][1], fBh[np][3]);
                }

            // ---- phase 3: Ah x Bl ----
            uint32_t fBl[4][4];
            #pragma unroll
            for (int np = 0; np < 4; np++)
                ldsm_x4(fBl[np], bb + OFF_BL + b_row_off + np * (16 * STRIDE) + ks * 32);
            #pragma unroll
            for (int mi = 0; mi < 4; mi++)
                #pragma unroll
                for (int np = 0; np < 4; np++) {
                    mma_bf16(acc[mi][np * 2 + 0], fAh[mi], fBl[np][0], fBl[np][2]);
                    mma_bf16(acc[mi][np * 2 + 1], fAh[mi], fBl[np][1], fBl[np][3]);
                }
        }
        if (it + 2 < NCH) {
            __syncthreads();           // all warps done reading buf
            copy_chunk(it + 2, buf);
        }
    }

    // ---- epilogue -----------------------------------------------------------
    const int lg = lane >> 2;          // row-in-group 0..7
    const int l2 = (lane & 3) * 2;     // col pair

    if constexpr (MODE != 3) {
        __nv_bfloat16* Hh = (MODE == 1) ? g_h1h : g_h2h;
        __nv_bfloat16* Hl = (MODE == 1) ? g_h1l : g_h2l;
        #pragma unroll
        for (int mi = 0; mi < 4; mi++) {
            const int pix = p0 + warp_m * 64 + mi * 16 + lg;
            const size_t r0 = ((size_t)b * NPIX + pix) * 512;
            const size_t r1 = r0 + 8 * 512;
            #pragma unroll
            for (int ni = 0; ni < 8; ni++) {
                const int chg = warp_n * 64 + ni * 8 + l2;   // 0..255
                const float b0 = sbias[chg], b1 = sbias[chg + 1];
                #pragma unroll
                for (int h = 0; h < 2; h++) {
                    const size_t row = h ? r1 : r0;
                    float v0 = acc[mi][ni][h * 2 + 0] + b0;
                    float v1 = acc[mi][ni][h * 2 + 1] + b1;
                    float s0, c0, s1, c1;
                    __sincosf(v0, &s0, &c0);
                    __sincosf(v1, &s1, &c1);
                    __nv_bfloat16 sh0 = __float2bfloat16(s0), sh1 = __float2bfloat16(s1);
                    __nv_bfloat16 ch0 = __float2bfloat16(c0), ch1 = __float2bfloat16(c1);
                    uint32_t shi = (uint32_t)__bfloat16_as_ushort(sh0) |
                                   ((uint32_t)__bfloat16_as_ushort(sh1) << 16);
                    uint32_t chi = (uint32_t)__bfloat16_as_ushort(ch0) |
                                   ((uint32_t)__bfloat16_as_ushort(ch1) << 16);
                    uint32_t slo = packbf2(s0 - __bfloat162float(sh0), s1 - __bfloat162float(sh1));
                    uint32_t clo = packbf2(c0 - __bfloat162float(ch0), c1 - __bfloat162float(ch1));
                    *(uint32_t*)(Hh + row + chg)       = shi;
                    *(uint32_t*)(Hh + row + chg + 256) = chi;
                    *(uint32_t*)(Hl + row + chg)       = slo;
                    *(uint32_t*)(Hl + row + chg + 256) = clo;
                }
            }
        }
    } else {
        // stage [128 px][260] fp32 in (reused) dynamic smem, then coalesced
        float* smf = (float*)dsm;
        __syncthreads();
        #pragma unroll
        for (int mi = 0; mi < 4; mi++) {
            const int pxl0 = warp_m * 64 + mi * 16 + lg;
            #pragma unroll
            for (int ni = 0; ni < 8; ni++) {
                const int chg = warp_n * 64 + ni * 8 + l2;
                const float b0 = sbias[chg], b1 = sbias[chg + 1];
                smf[pxl0 * 260 + chg]           = acc[mi][ni][0] + b0;
                smf[pxl0 * 260 + chg + 1]       = acc[mi][ni][1] + b1;
                smf[(pxl0 + 8) * 260 + chg]     = acc[mi][ni][2] + b0;
                smf[(pxl0 + 8) * 260 + chg + 1] = acc[mi][ni][3] + b1;
            }
        }
        __syncthreads();
        const int ch = tid;                // 0..255
        float* orow = out + ((size_t)b * 256 + ch) * NPIX + p0;
        #pragma unroll
        for (int g = 0; g < 32; g++) {
            float4 v;
            v.x = smf[(g * 4 + 0) * 260 + ch];
            v.y = smf[(g * 4 + 1) * 260 + ch];
            v.z = smf[(g * 4 + 2) * 260 + ch];
            v.w = smf[(g * 4 + 3) * 260 + ch];
            *(float4*)(orow + g * 4) = v;
        }
    }
}

// -------------------- launch ------------------------------------------------
extern "C" void kernel_launch(void* const* d_in, const int* in_sizes, int n_in,
                              void* d_out, int out_size) {
    const float* x           = (const float*)d_in[0];
    const float* lat         = (const float*)d_in[1];
    const float* k_in_mix    = (const float*)d_in[2];
    const float* k_mid_mix   = (const float*)d_in[3];
    const float* k_out_mix   = (const float*)d_in[4];
    const float* k_short_mix = (const float*)d_in[5];
    const float* b_in_mix    = (const float*)d_in[6];
    const float* b_mid_mix   = (const float*)d_in[7];
    const float* b_out_mix   = (const float*)d_in[8];
    const float* b_short_mix = (const float*)d_in[9];
    const float* w_dyna      = (const float*)d_in[10];
    const float* b_dyna      = (const float*)d_in[11];
    float* out = (float*)d_out;

    cudaFuncSetAttribute(gemm_stage<1>, cudaFuncAttributeMaxDynamicSharedMemorySize, SMEM_DYN);
    cudaFuncSetAttribute(gemm_stage<2>, cudaFuncAttributeMaxDynamicSharedMemorySize, SMEM_DYN);
    cudaFuncSetAttribute(gemm_stage<3>, cudaFuncAttributeMaxDynamicSharedMemorySize, SMEM_DYN);

    mix_kernel<<<1, 128>>>(lat, w_dyna, b_dyna);
    prep_kernel<<<1537, 256>>>(k_in_mix, k_mid_mix, k_out_mix, k_short_mix,
                               b_in_mix, b_mid_mix, b_out_mix, b_short_mix);
    xt_kernel<<<dim3(128, 8, 16), dim3(32, 8)>>>(x);
    gemm_stage<1><<<dim3(32, 16), 256, SMEM_DYN>>>(out);
    gemm_stage<2><<<dim3(32, 16), 256, SMEM_DYN>>>(out);
    gemm_stage<3><<<dim3(32, 16), 256, SMEM_DYN>>>(out);
}

// round 8
// speedup vs baseline: 1.7087x; 1.7087x over previous
#include <cuda_runtime.h>
#include <cuda_fp16.h>
#include <cstdint>

// ============================================================================
// MixResidualBlockC via warp-level fp16 mma.sync, 2-term fp32 emulation:
//   x*w ~= fp16(x)*wh + fp16(x)*wl   (weights 2-split fp16; activations fp16)
//   stage1: h1 = sincos(W1[256,256] @ xt)           (pixel-major fp16)
//   stage2: h2 = sincos(W2[256,512] @ h1)
//   stage3: out = W3[256,768] @ [h2 ; xt] + b3      (W3 = [k_out | k_short])
// CTA 128px x 128ch, 8 warps (2x4), warp tile 64x32, BK=32, 80B rows,
// 2 CTAs/SM. R8: 3 MMA terms -> 2 (bf16 3-split -> fp16 weight 2-split).
// ============================================================================

#define NPIX 4096
#define NB 16
#define STRIDE 80                      // bytes per 32-fp16 smem row (padded)
#define PLANE (128 * STRIDE)           // 10240 B per plane tile
#define BUFSZ (3 * PLANE)              // A | Bh | Bl = 30720 B
#define SMEM_DYN 67584                 // max(2*BUFSZ=61440, 128*132*4=67584)

// -------------------- device scratch --------------------------------------
__device__ float g_mix[NB * 8];
__device__ float g_b1[NB * 256], g_b2[NB * 256], g_b3[NB * 256];
__device__ __half g_w1h[NB * 256 * 256], g_w1l[NB * 256 * 256];
__device__ __half g_w2h[NB * 256 * 512], g_w2l[NB * 256 * 512];
__device__ __half g_w3h[NB * 256 * 768], g_w3l[NB * 256 * 768];
__device__ __half g_xt[(size_t)NB * NPIX * 256];
__device__ __half g_h1[(size_t)NB * NPIX * 512];
__device__ __half g_h2[(size_t)NB * NPIX * 512];

// -------------------- PTX helpers (all arch-portable) ----------------------
__device__ __forceinline__ uint32_t smem_u32(const void* p) {
    uint32_t a;
    asm("{ .reg .u64 t; cvta.to.shared.u64 t, %1; cvt.u32.u64 %0, t; }" : "=r"(a) : "l"(p));
    return a;
}
__device__ __forceinline__ void cpa16(uint32_t dst, const void* src) {
    asm volatile("cp.async.cg.shared.global [%0], [%1], 16;" :: "r"(dst), "l"(src));
}
__device__ __forceinline__ void cpa_commit() { asm volatile("cp.async.commit_group;"); }

__device__ __forceinline__ void ldsm_x4(uint32_t* r, uint32_t addr) {
    asm volatile("ldmatrix.sync.aligned.m8n8.x4.shared.b16 {%0,%1,%2,%3}, [%4];"
                 : "=r"(r[0]), "=r"(r[1]), "=r"(r[2]), "=r"(r[3]) : "r"(addr));
}
__device__ __forceinline__ void mma_f16(float* d, const uint32_t* a,
                                        uint32_t b0, uint32_t b1) {
    asm volatile(
        "mma.sync.aligned.m16n8k16.row.col.f32.f16.f16.f32 "
        "{%0,%1,%2,%3}, {%4,%5,%6,%7}, {%8,%9}, {%0,%1,%2,%3};"
        : "+f"(d[0]), "+f"(d[1]), "+f"(d[2]), "+f"(d[3])
        : "r"(a[0]), "r"(a[1]), "r"(a[2]), "r"(a[3]), "r"(b0), "r"(b1));
}
__device__ __forceinline__ uint32_t packh2(float a, float b) {
    __half h0 = __float2half_rn(a), h1 = __float2half_rn(b);
    return (uint32_t)__half_as_ushort(h0) | ((uint32_t)__half_as_ushort(h1) << 16);
}

// -------------------- K0: mixing coefficients ------------------------------
__global__ void mix_kernel(const float* __restrict__ lat, const float* __restrict__ wd,
                           const float* __restrict__ bd) {
    int t = threadIdx.x;
    if (t < 128) {
        int b = t >> 3, m = t & 7;
        float a = bd[m];
        const float* lp = lat + b * 512;
        const float* wp = wd + m * 512;
        #pragma unroll 8
        for (int l = 0; l < 512; l++) a += lp[l] * wp[l];
        g_mix[t] = a;
    }
}

// -------------------- K1: weight mixing + fp16 hi/lo split -----------------
__global__ void prep_kernel(const float* __restrict__ kin, const float* __restrict__ kmid,
                            const float* __restrict__ kout, const float* __restrict__ ksh,
                            const float* __restrict__ bin, const float* __restrict__ bmid,
                            const float* __restrict__ bout, const float* __restrict__ bsh) {
    __shared__ float smix[128];
    if (threadIdx.x < 128) smix[threadIdx.x] = g_mix[threadIdx.x];
    __syncthreads();
    int p = blockIdx.x * 256 + threadIdx.x;
    float v[8];

    if (p < 65536) {  // w1 (k_in)
        #pragma unroll
        for (int m = 0; m < 8; m++) v[m] = kin[m * 65536 + p];
        #pragma unroll
        for (int b = 0; b < NB; b++) {
            float a = 0.f;
            #pragma unroll
            for (int m = 0; m < 8; m++) a += smix[b * 8 + m] * v[m];
            __half h = __float2half_rn(a);
            g_w1h[b * 65536 + p] = h;
            g_w1l[b * 65536 + p] = __float2half_rn(a - __half2float(h));
        }
    } else if (p < 196608) {  // w2 (k_mid)
        int q = p - 65536;
        #pragma unroll
        for (int m = 0; m < 8; m++) v[m] = kmid[m * 131072 + q];
        #pragma unroll
        for (int b = 0; b < NB; b++) {
            float a = 0.f;
            #pragma unroll
            for (int m = 0; m < 8; m++) a += smix[b * 8 + m] * v[m];
            __half h = __float2half_rn(a);
            g_w2h[b * 131072 + q] = h;
            g_w2l[b * 131072 + q] = __float2half_rn(a - __half2float(h));
        }
    } else if (p < 327680) {  // w3 k_out part: cols [0,512)
        int q = p - 196608;
        int o = q >> 9, i = q & 511;
        #pragma unroll
        for (int m = 0; m < 8; m++) v[m] = kout[m * 131072 + q];
        int di = o * 768 + i;
        #pragma unroll
        for (int b = 0; b < NB; b++) {
            float a = 0.f;
            #pragma unroll
            for (int m = 0; m < 8; m++) a += smix[b * 8 + m] * v[m];
            __half h = __float2half_rn(a);
            g_w3h[b * 196608 + di] = h;
            g_w3l[b * 196608 + di] = __float2half_rn(a - __half2float(h));
        }
    } else if (p < 393216) {  // w3 k_short part: cols [512,768)
        int q = p - 327680;
        int o = q >> 8, i = q & 255;
        #pragma unroll
        for (int m = 0; m < 8; m++) v[m] = ksh[m * 65536 + q];
        int di = o * 768 + 512 + i;
        #pragma unroll
        for (int b = 0; b < NB; b++) {
            float a = 0.f;
            #pragma unroll
            for (int m = 0; m < 8; m++) a += smix[b * 8 + m] * v[m];
            __half h = __float2half_rn(a);
            g_w3h[b * 196608 + di] = h;
            g_w3l[b * 196608 + di] = __float2half_rn(a - __half2float(h));
        }
    } else if (p < 393472) {  // biases
        int r = p - 393216;
        float vi[8], vm[8], vo[8];
        #pragma unroll
        for (int m = 0; m < 8; m++) {
            vi[m] = bin[m * 256 + r];
            vm[m] = bmid[m * 256 + r];
            vo[m] = bout[m * 256 + r] + bsh[m * 256 + r];
        }
        #pragma unroll
        for (int b = 0; b < NB; b++) {
            float a1 = 0.f, a2 = 0.f, a3 = 0.f;
            #pragma unroll
            for (int m = 0; m < 8; m++) {
                float mx = smix[b * 8 + m];
                a1 += mx * vi[m]; a2 += mx * vm[m]; a3 += mx * vo[m];
            }
            g_b1[b * 256 + r] = a1;
            g_b2[b * 256 + r] = a2;
            g_b3[b * 256 + r] = a3;
        }
    }
}

// -------------------- K2: x transpose  x[b,c,p] -> xt[b,p,c] (fp16) --------
__global__ void xt_kernel(const float* __restrict__ x) {
    __shared__ float ts[32][33];
    int b = blockIdx.z, p0 = blockIdx.x * 32, c0 = blockIdx.y * 32;
    const float* src = x + ((size_t)b * 256 + c0) * NPIX + p0;
    for (int r = threadIdx.y; r < 32; r += 8)
        ts[r][threadIdx.x] = src[(size_t)r * NPIX + threadIdx.x];
    __syncthreads();
    int lane = threadIdx.x;
    for (int pr = threadIdx.y; pr < 32; pr += 8) {
        size_t di = ((size_t)b * NPIX + p0 + pr) * 256 + c0 + lane;
        g_xt[di] = __float2half_rn(ts[lane][pr]);
    }
}

// -------------------- GEMM stage (mma.sync fp16 2-term) --------------------
template <int MODE>  // 1,2,3
__global__ void __launch_bounds__(256, 2)
gemm_stage(float* __restrict__ out) {
    constexpr int K = (MODE == 1) ? 256 : (MODE == 2) ? 512 : 768;
    constexpr int NCH = K / 32;
    constexpr int AROW = (MODE == 1) ? 256 : 512;

    extern __shared__ __align__(16) char dsm[];
    const uint32_t sbase = smem_u32(dsm);
    __shared__ float sbias[128];

    const int tid = threadIdx.x;
    const int lane = tid & 31;
    const int wid = tid >> 5;
    const int warp_m = wid & 1;       // 0..1  (64 px each)
    const int warp_n = wid >> 1;      // 0..3  (32 ch each)
    const int b = blockIdx.z;
    const int p0 = blockIdx.x * 128;
    const int cg0 = blockIdx.y * 128;

    const __half *A, *Bh, *Bl;
    const float* bias;
    if constexpr (MODE == 1) {
        A = g_xt + (size_t)b * NPIX * 256;
        Bh = g_w1h + (size_t)b * 65536;  Bl = g_w1l + (size_t)b * 65536;
        bias = g_b1 + b * 256;
    } else if constexpr (MODE == 2) {
        A = g_h1 + (size_t)b * NPIX * 512;
        Bh = g_w2h + (size_t)b * 131072; Bl = g_w2l + (size_t)b * 131072;
        bias = g_b2 + b * 256;
    } else {
        A = g_h2 + (size_t)b * NPIX * 512;
        Bh = g_w3h + (size_t)b * 196608; Bl = g_w3l + (size_t)b * 196608;
        bias = g_b3 + b * 256;
    }
    const __half* Xt = g_xt + (size_t)b * NPIX * 256;  // MODE3 tail

    if (tid < 128) sbias[tid] = bias[cg0 + tid];

    // ---- chunk copier: 1536 x 16B (A | Bh | Bl, 128 rows x 4 units) -------
    auto copy_chunk = [&](int ch, int buf) {
        const int k0 = ch * 32;
        const uint32_t bb = sbase + buf * BUFSZ;
        const __half* pA = A;
        int acol = k0, arow = AROW;
        if (MODE == 3 && k0 >= 512) { pA = Xt; acol = k0 - 512; arow = 256; }
        #pragma unroll
        for (int j = 0; j < 6; j++) {
            int u = tid + j * 256;
            int plane = u >> 9;           // 0 A, 1 Bh, 2 Bl
            int r = (u >> 2) & 127;
            int c = u & 3;
            uint32_t dst = bb + plane * PLANE + r * STRIDE + c * 16;
            const __half* src;
            if (plane == 0)      src = pA + (size_t)(p0 + r) * arow + acol + c * 8;
            else if (plane == 1) src = Bh + (size_t)(cg0 + r) * K + k0 + c * 8;
            else                 src = Bl + (size_t)(cg0 + r) * K + k0 + c * 8;
            cpa16(dst, src);
        }
        cpa_commit();
    };

    // ---- ldmatrix lane address offsets ----
    const int a_row_off = (warp_m * 64 + (lane & 15)) * STRIDE + ((lane >> 4) & 1) * 16;
    const int b_row_off = (warp_n * 32 + (lane & 15)) * STRIDE + ((lane >> 4) & 1) * 16;

    float acc[4][4][4];
    #pragma unroll
    for (int i = 0; i < 4; i++)
        #pragma unroll
        for (int j = 0; j < 4; j++)
            #pragma unroll
            for (int q = 0; q < 4; q++) acc[i][j][q] = 0.f;

    copy_chunk(0, 0);
    if (NCH > 1) copy_chunk(1, 1);

    for (int it = 0; it < NCH; it++) {
        const int buf = it & 1;
        if (it + 1 < NCH) asm volatile("cp.async.wait_group 1;" ::: "memory");
        else              asm volatile("cp.async.wait_group 0;" ::: "memory");
        __syncthreads();
        const uint32_t bb = sbase + buf * BUFSZ;

        #pragma unroll
        for (int ks = 0; ks < 2; ks++) {
            // ---- phase 1: A x Bh ----
            uint32_t fA[4][4], fBh[2][4];
            #pragma unroll
            for (int mi = 0; mi < 4; mi++)
                ldsm_x4(fA[mi], bb + a_row_off + mi * (16 * STRIDE) + ks * 32);
            #pragma unroll
            for (int np = 0; np < 2; np++)
                ldsm_x4(fBh[np], bb + PLANE + b_row_off + np * (16 * STRIDE) + ks * 32);
            #pragma unroll
            for (int mi = 0; mi < 4; mi++)
                #pragma unroll
                for (int np = 0; np < 2; np++) {
                    mma_f16(acc[mi][np * 2 + 0], fA[mi], fBh[np][0], fBh[np][2]);
                    mma_f16(acc[mi][np * 2 + 1], fA[mi], fBh[np][1], fBh[np][3]);
                }

            // ---- phase 2: A x Bl ----
            uint32_t fBl[2][4];
            #pragma unroll
            for (int np = 0; np < 2; np++)
                ldsm_x4(fBl[np], bb + 2 * PLANE + b_row_off + np * (16 * STRIDE) + ks * 32);
            #pragma unroll
            for (int mi = 0; mi < 4; mi++)
                #pragma unroll
                for (int np = 0; np < 2; np++) {
                    mma_f16(acc[mi][np * 2 + 0], fA[mi], fBl[np][0], fBl[np][2]);
                    mma_f16(acc[mi][np * 2 + 1], fA[mi], fBl[np][1], fBl[np][3]);
                }
        }
        if (it + 2 < NCH) {
            __syncthreads();           // all warps done reading buf
            copy_chunk(it + 2, buf);
        }
    }

    // ---- epilogue -----------------------------------------------------------
    const int lg = lane >> 2;          // row-in-group 0..7
    const int l2 = (lane & 3) * 2;     // col pair

    if constexpr (MODE != 3) {
        __half* H = (MODE == 1) ? g_h1 : g_h2;
        #pragma unroll
        for (int mi = 0; mi < 4; mi++) {
            const int pix = p0 + warp_m * 64 + mi * 16 + lg;
            const size_t r0 = ((size_t)b * NPIX + pix) * 512;
            const size_t r1 = r0 + 8 * 512;
            #pragma unroll
            for (int ni = 0; ni < 4; ni++) {
                const int chl = warp_n * 32 + ni * 8 + l2;   // local 0..127
                const int chg = cg0 + chl;                   // global 0..255
                const float b0 = sbias[chl], b1 = sbias[chl + 1];
                #pragma unroll
                for (int h = 0; h < 2; h++) {
                    const size_t row = h ? r1 : r0;
                    float v0 = acc[mi][ni][h * 2 + 0] + b0;
                    float v1 = acc[mi][ni][h * 2 + 1] + b1;
                    float s0, c0, s1, c1;
                    __sincosf(v0, &s0, &c0);
                    __sincosf(v1, &s1, &c1);
                    *(uint32_t*)(H + row + chg)       = packh2(s0, s1);
                    *(uint32_t*)(H + row + chg + 256) = packh2(c0, c1);
                }
            }
        }
    } else {
        // stage smem [128 px][132] fp32 then coalesced channel-major writes
        float* smf = (float*)dsm;
        __syncthreads();
        #pragma unroll
        for (int mi = 0; mi < 4; mi++) {
            const int pxl0 = warp_m * 64 + mi * 16 + lg;
            #pragma unroll
            for (int ni = 0; ni < 4; ni++) {
                const int chl = warp_n * 32 + ni * 8 + l2;
                const float b0 = sbias[chl], b1 = sbias[chl + 1];
                smf[pxl0 * 132 + chl]           = acc[mi][ni][0] + b0;
                smf[pxl0 * 132 + chl + 1]       = acc[mi][ni][1] + b1;
                smf[(pxl0 + 8) * 132 + chl]     = acc[mi][ni][2] + b0;
                smf[(pxl0 + 8) * 132 + chl + 1] = acc[mi][ni][3] + b1;
            }
        }
        __syncthreads();
        const int ch = tid >> 1;           // 0..127
        const int pxh = (tid & 1) * 64;
        float* orow = out + ((size_t)b * 256 + cg0 + ch) * NPIX + p0 + pxh;
        #pragma unroll
        for (int g = 0; g < 16; g++) {
            float4 v;
            v.x = smf[(pxh + g * 4 + 0) * 132 + ch];
            v.y = smf[(pxh + g * 4 + 1) * 132 + ch];
            v.z = smf[(pxh + g * 4 + 2) * 132 + ch];
            v.w = smf[(pxh + g * 4 + 3) * 132 + ch];
            *(float4*)(orow + g * 4) = v;
        }
    }
}

// -------------------- launch ------------------------------------------------
extern "C" void kernel_launch(void* const* d_in, const int* in_sizes, int n_in,
                              void* d_out, int out_size) {
    const float* x           = (const float*)d_in[0];
    const float* lat         = (const float*)d_in[1];
    const float* k_in_mix    = (const float*)d_in[2];
    const float* k_mid_mix   = (const float*)d_in[3];
    const float* k_out_mix   = (const float*)d_in[4];
    const float* k_short_mix = (const float*)d_in[5];
    const float* b_in_mix    = (const float*)d_in[6];
    const float* b_mid_mix   = (const float*)d_in[7];
    const float* b_out_mix   = (const float*)d_in[8];
    const float* b_short_mix = (const float*)d_in[9];
    const float* w_dyna      = (const float*)d_in[10];
    const float* b_dyna      = (const float*)d_in[11];
    float* out = (float*)d_out;

    cudaFuncSetAttribute(gemm_stage<1>, cudaFuncAttributeMaxDynamicSharedMemorySize, SMEM_DYN);
    cudaFuncSetAttribute(gemm_stage<2>, cudaFuncAttributeMaxDynamicSharedMemorySize, SMEM_DYN);
    cudaFuncSetAttribute(gemm_stage<3>, cudaFuncAttributeMaxDynamicSharedMemorySize, SMEM_DYN);

    mix_kernel<<<1, 128>>>(lat, w_dyna, b_dyna);
    prep_kernel<<<1537, 256>>>(k_in_mix, k_mid_mix, k_out_mix, k_short_mix,
                               b_in_mix, b_mid_mix, b_out_mix, b_short_mix);
    xt_kernel<<<dim3(128, 8, 16), dim3(32, 8)>>>(x);
    gemm_stage<1><<<dim3(32, 2, 16), 256, SMEM_DYN>>>(out);
    gemm_stage<2><<<dim3(32, 2, 16), 256, SMEM_DYN>>>(out);
    gemm_stage<3><<<dim3(32, 2, 16), 256, SMEM_DYN>>>(out);
}

// round 9
// speedup vs baseline: 2.3075x; 1.3504x over previous
#include <cuda_runtime.h>
#include <cuda_fp16.h>
#include <cstdint>

// ============================================================================
// MixResidualBlockC via warp-level fp16 mma.sync (pure fp16 inputs, fp32 acc):
//   stage1: h1 = sincos(W1[256,256] @ xt)           (pixel-major fp16)
//   stage2: h2 = sincos(W2[256,512] @ h1)
//   stage3: out = W3[256,768] @ [h2 ; xt] + b3      (W3 = [k_out | k_short])
// CTA 128px x 128ch, 8 warps (2x4), warp tile 64x32, BK=32, 80B rows,
// 2 CTAs/SM. R9: 2 MMA terms -> 1 (single fp16 weights; time tracks MMA count).
// ============================================================================

#define NPIX 4096
#define NB 16
#define STRIDE 80                      // bytes per 32-fp16 smem row (padded)
#define PLANE (128 * STRIDE)           // 10240 B per plane tile
#define BUFSZ (2 * PLANE)              // A | B = 20480 B
#define SMEM_G 40960                   // 2 buffers (stages 1,2)
#define SMEM_G3 67584                  // stage 3: max(40960, 128*132*4)

// -------------------- device scratch --------------------------------------
__device__ float g_mix[NB * 8];
__device__ float g_b1[NB * 256], g_b2[NB * 256], g_b3[NB * 256];
__device__ __half g_w1[NB * 256 * 256];
__device__ __half g_w2[NB * 256 * 512];
__device__ __half g_w3[NB * 256 * 768];
__device__ __half g_xt[(size_t)NB * NPIX * 256];
__device__ __half g_h1[(size_t)NB * NPIX * 512];
__device__ __half g_h2[(size_t)NB * NPIX * 512];

// -------------------- PTX helpers (all arch-portable) ----------------------
__device__ __forceinline__ uint32_t smem_u32(const void* p) {
    uint32_t a;
    asm("{ .reg .u64 t; cvta.to.shared.u64 t, %1; cvt.u32.u64 %0, t; }" : "=r"(a) : "l"(p));
    return a;
}
__device__ __forceinline__ void cpa16(uint32_t dst, const void* src) {
    asm volatile("cp.async.cg.shared.global [%0], [%1], 16;" :: "r"(dst), "l"(src));
}
__device__ __forceinline__ void cpa_commit() { asm volatile("cp.async.commit_group;"); }

__device__ __forceinline__ void ldsm_x4(uint32_t* r, uint32_t addr) {
    asm volatile("ldmatrix.sync.aligned.m8n8.x4.shared.b16 {%0,%1,%2,%3}, [%4];"
                 : "=r"(r[0]), "=r"(r[1]), "=r"(r[2]), "=r"(r[3]) : "r"(addr));
}
__device__ __forceinline__ void mma_f16(float* d, const uint32_t* a,
                                        uint32_t b0, uint32_t b1) {
    asm volatile(
        "mma.sync.aligned.m16n8k16.row.col.f32.f16.f16.f32 "
        "{%0,%1,%2,%3}, {%4,%5,%6,%7}, {%8,%9}, {%0,%1,%2,%3};"
        : "+f"(d[0]), "+f"(d[1]), "+f"(d[2]), "+f"(d[3])
        : "r"(a[0]), "r"(a[1]), "r"(a[2]), "r"(a[3]), "r"(b0), "r"(b1));
}
__device__ __forceinline__ uint32_t packh2(float a, float b) {
    __half h0 = __float2half_rn(a), h1 = __float2half_rn(b);
    return (uint32_t)__half_as_ushort(h0) | ((uint32_t)__half_as_ushort(h1) << 16);
}

// -------------------- K0: mixing coefficients ------------------------------
__global__ void mix_kernel(const float* __restrict__ lat, const float* __restrict__ wd,
                           const float* __restrict__ bd) {
    int t = threadIdx.x;
    if (t < 128) {
        int b = t >> 3, m = t & 7;
        float a = bd[m];
        const float* lp = lat + b * 512;
        const float* wp = wd + m * 512;
        #pragma unroll 8
        for (int l = 0; l < 512; l++) a += lp[l] * wp[l];
        g_mix[t] = a;
    }
}

// -------------------- K1: weight mixing -> fp16 ----------------------------
__global__ void prep_kernel(const float* __restrict__ kin, const float* __restrict__ kmid,
                            const float* __restrict__ kout, const float* __restrict__ ksh,
                            const float* __restrict__ bin, const float* __restrict__ bmid,
                            const float* __restrict__ bout, const float* __restrict__ bsh) {
    __shared__ float smix[128];
    if (threadIdx.x < 128) smix[threadIdx.x] = g_mix[threadIdx.x];
    __syncthreads();
    int p = blockIdx.x * 256 + threadIdx.x;
    float v[8];

    if (p < 65536) {  // w1 (k_in)
        #pragma unroll
        for (int m = 0; m < 8; m++) v[m] = kin[m * 65536 + p];
        #pragma unroll
        for (int b = 0; b < NB; b++) {
            float a = 0.f;
            #pragma unroll
            for (int m = 0; m < 8; m++) a += smix[b * 8 + m] * v[m];
            g_w1[b * 65536 + p] = __float2half_rn(a);
        }
    } else if (p < 196608) {  // w2 (k_mid)
        int q = p - 65536;
        #pragma unroll
        for (int m = 0; m < 8; m++) v[m] = kmid[m * 131072 + q];
        #pragma unroll
        for (int b = 0; b < NB; b++) {
            float a = 0.f;
            #pragma unroll
            for (int m = 0; m < 8; m++) a += smix[b * 8 + m] * v[m];
            g_w2[b * 131072 + q] = __float2half_rn(a);
        }
    } else if (p < 327680) {  // w3 k_out part: cols [0,512)
        int q = p - 196608;
        int o = q >> 9, i = q & 511;
        #pragma unroll
        for (int m = 0; m < 8; m++) v[m] = kout[m * 131072 + q];
        int di = o * 768 + i;
        #pragma unroll
        for (int b = 0; b < NB; b++) {
            float a = 0.f;
            #pragma unroll
            for (int m = 0; m < 8; m++) a += smix[b * 8 + m] * v[m];
            g_w3[b * 196608 + di] = __float2half_rn(a);
        }
    } else if (p < 393216) {  // w3 k_short part: cols [512,768)
        int q = p - 327680;
        int o = q >> 8, i = q & 255;
        #pragma unroll
        for (int m = 0; m < 8; m++) v[m] = ksh[m * 65536 + q];
        int di = o * 768 + 512 + i;
        #pragma unroll
        for (int b = 0; b < NB; b++) {
            float a = 0.f;
            #pragma unroll
            for (int m = 0; m < 8; m++) a += smix[b * 8 + m] * v[m];
            g_w3[b * 196608 + di] = __float2half_rn(a);
        }
    } else if (p < 393472) {  // biases
        int r = p - 393216;
        float vi[8], vm[8], vo[8];
        #pragma unroll
        for (int m = 0; m < 8; m++) {
            vi[m] = bin[m * 256 + r];
            vm[m] = bmid[m * 256 + r];
            vo[m] = bout[m * 256 + r] + bsh[m * 256 + r];
        }
        #pragma unroll
        for (int b = 0; b < NB; b++) {
            float a1 = 0.f, a2 = 0.f, a3 = 0.f;
            #pragma unroll
            for (int m = 0; m < 8; m++) {
                float mx = smix[b * 8 + m];
                a1 += mx * vi[m]; a2 += mx * vm[m]; a3 += mx * vo[m];
            }
            g_b1[b * 256 + r] = a1;
            g_b2[b * 256 + r] = a2;
            g_b3[b * 256 + r] = a3;
        }
    }
}

// -------------------- K2: x transpose  x[b,c,p] -> xt[b,p,c] (fp16) --------
__global__ void xt_kernel(const float* __restrict__ x) {
    __shared__ float ts[32][33];
    int b = blockIdx.z, p0 = blockIdx.x * 32, c0 = blockIdx.y * 32;
    const float* src = x + ((size_t)b * 256 + c0) * NPIX + p0;
    for (int r = threadIdx.y; r < 32; r += 8)
        ts[r][threadIdx.x] = src[(size_t)r * NPIX + threadIdx.x];
    __syncthreads();
    int lane = threadIdx.x;
    for (int pr = threadIdx.y; pr < 32; pr += 8) {
        size_t di = ((size_t)b * NPIX + p0 + pr) * 256 + c0 + lane;
        g_xt[di] = __float2half_rn(ts[lane][pr]);
    }
}

// -------------------- GEMM stage (pure fp16 mma.sync) ----------------------
template <int MODE>  // 1,2,3
__global__ void __launch_bounds__(256, 2)
gemm_stage(float* __restrict__ out) {
    constexpr int K = (MODE == 1) ? 256 : (MODE == 2) ? 512 : 768;
    constexpr int NCH = K / 32;
    constexpr int AROW = (MODE == 1) ? 256 : 512;

    extern __shared__ __align__(16) char dsm[];
    const uint32_t sbase = smem_u32(dsm);
    __shared__ float sbias[128];

    const int tid = threadIdx.x;
    const int lane = tid & 31;
    const int wid = tid >> 5;
    const int warp_m = wid & 1;       // 0..1  (64 px each)
    const int warp_n = wid >> 1;      // 0..3  (32 ch each)
    const int b = blockIdx.z;
    const int p0 = blockIdx.x * 128;
    const int cg0 = blockIdx.y * 128;

    const __half *A, *B;
    const float* bias;
    if constexpr (MODE == 1) {
        A = g_xt + (size_t)b * NPIX * 256;
        B = g_w1 + (size_t)b * 65536;
        bias = g_b1 + b * 256;
    } else if constexpr (MODE == 2) {
        A = g_h1 + (size_t)b * NPIX * 512;
        B = g_w2 + (size_t)b * 131072;
        bias = g_b2 + b * 256;
    } else {
        A = g_h2 + (size_t)b * NPIX * 512;
        B = g_w3 + (size_t)b * 196608;
        bias = g_b3 + b * 256;
    }
    const __half* Xt = g_xt + (size_t)b * NPIX * 256;  // MODE3 tail

    if (tid < 128) sbias[tid] = bias[cg0 + tid];

    // ---- chunk copier: 1024 x 16B (A | B, 128 rows x 4 units each) --------
    auto copy_chunk = [&](int ch, int buf) {
        const int k0 = ch * 32;
        const uint32_t bb = sbase + buf * BUFSZ;
        const __half* pA = A;
        int acol = k0, arow = AROW;
        if (MODE == 3 && k0 >= 512) { pA = Xt; acol = k0 - 512; arow = 256; }
        #pragma unroll
        for (int j = 0; j < 4; j++) {
            int u = tid + j * 256;
            int plane = u >> 9;           // 0 A, 1 B
            int r = (u >> 2) & 127;
            int c = u & 3;
            uint32_t dst = bb + plane * PLANE + r * STRIDE + c * 16;
            const __half* src;
            if (plane == 0) src = pA + (size_t)(p0 + r) * arow + acol + c * 8;
            else            src = B + (size_t)(cg0 + r) * K + k0 + c * 8;
            cpa16(dst, src);
        }
        cpa_commit();
    };

    // ---- ldmatrix lane address offsets ----
    const int a_row_off = (warp_m * 64 + (lane & 15)) * STRIDE + ((lane >> 4) & 1) * 16;
    const int b_row_off = (warp_n * 32 + (lane & 15)) * STRIDE + ((lane >> 4) & 1) * 16;

    float acc[4][4][4];
    #pragma unroll
    for (int i = 0; i < 4; i++)
        #pragma unroll
        for (int j = 0; j < 4; j++)
            #pragma unroll
            for (int q = 0; q < 4; q++) acc[i][j][q] = 0.f;

    copy_chunk(0, 0);
    if (NCH > 1) copy_chunk(1, 1);

    for (int it = 0; it < NCH; it++) {
        const int buf = it & 1;
        if (it + 1 < NCH) asm volatile("cp.async.wait_group 1;" ::: "memory");
        else              asm volatile("cp.async.wait_group 0;" ::: "memory");
        __syncthreads();
        const uint32_t bb = sbase + buf * BUFSZ;

        #pragma unroll
        for (int ks = 0; ks < 2; ks++) {
            uint32_t fA[4][4], fB[2][4];
            #pragma unroll
            for (int mi = 0; mi < 4; mi++)
                ldsm_x4(fA[mi], bb + a_row_off + mi * (16 * STRIDE) + ks * 32);
            #pragma unroll
            for (int np = 0; np < 2; np++)
                ldsm_x4(fB[np], bb + PLANE + b_row_off + np * (16 * STRIDE) + ks * 32);
            #pragma unroll
            for (int mi = 0; mi < 4; mi++)
                #pragma unroll
                for (int np = 0; np < 2; np++) {
                    mma_f16(acc[mi][np * 2 + 0], fA[mi], fB[np][0], fB[np][2]);
                    mma_f16(acc[mi][np * 2 + 1], fA[mi], fB[np][1], fB[np][3]);
                }
        }
        if (it + 2 < NCH) {
            __syncthreads();           // all warps done reading buf
            copy_chunk(it + 2, buf);
        }
    }

    // ---- epilogue -----------------------------------------------------------
    const int lg = lane >> 2;          // row-in-group 0..7
    const int l2 = (lane & 3) * 2;     // col pair

    if constexpr (MODE != 3) {
        __half* H = (MODE == 1) ? g_h1 : g_h2;
        #pragma unroll
        for (int mi = 0; mi < 4; mi++) {
            const int pix = p0 + warp_m * 64 + mi * 16 + lg;
            const size_t r0 = ((size_t)b * NPIX + pix) * 512;
            const size_t r1 = r0 + 8 * 512;
            #pragma unroll
            for (int ni = 0; ni < 4; ni++) {
                const int chl = warp_n * 32 + ni * 8 + l2;   // local 0..127
                const int chg = cg0 + chl;                   // global 0..255
                const float b0 = sbias[chl], b1 = sbias[chl + 1];
                #pragma unroll
                for (int h = 0; h < 2; h++) {
                    const size_t row = h ? r1 : r0;
                    float v0 = acc[mi][ni][h * 2 + 0] + b0;
                    float v1 = acc[mi][ni][h * 2 + 1] + b1;
                    float s0, c0, s1, c1;
                    __sincosf(v0, &s0, &c0);
                    __sincosf(v1, &s1, &c1);
                    *(uint32_t*)(H + row + chg)       = packh2(s0, s1);
                    *(uint32_t*)(H + row + chg + 256) = packh2(c0, c1);
                }
            }
        }
    } else {
        // stage smem [128 px][132] fp32 then coalesced channel-major writes
        float* smf = (float*)dsm;
        __syncthreads();
        #pragma unroll
        for (int mi = 0; mi < 4; mi++) {
            const int pxl0 = warp_m * 64 + mi * 16 + lg;
            #pragma unroll
            for (int ni = 0; ni < 4; ni++) {
                const int chl = warp_n * 32 + ni * 8 + l2;
                const float b0 = sbias[chl], b1 = sbias[chl + 1];
                smf[pxl0 * 132 + chl]           = acc[mi][ni][0] + b0;
                smf[pxl0 * 132 + chl + 1]       = acc[mi][ni][1] + b1;
                smf[(pxl0 + 8) * 132 + chl]     = acc[mi][ni][2] + b0;
                smf[(pxl0 + 8) * 132 + chl + 1] = acc[mi][ni][3] + b1;
            }
        }
        __syncthreads();
        const int ch = tid >> 1;           // 0..127
        const int pxh = (tid & 1) * 64;
        float* orow = out + ((size_t)b * 256 + cg0 + ch) * NPIX + p0 + pxh;
        #pragma unroll
        for (int g = 0; g < 16; g++) {
            float4 v;
            v.x = smf[(pxh + g * 4 + 0) * 132 + ch];
            v.y = smf[(pxh + g * 4 + 1) * 132 + ch];
            v.z = smf[(pxh + g * 4 + 2) * 132 + ch];
            v.w = smf[(pxh + g * 4 + 3) * 132 + ch];
            *(float4*)(orow + g * 4) = v;
        }
    }
}

// -------------------- launch ------------------------------------------------
extern "C" void kernel_launch(void* const* d_in, const int* in_sizes, int n_in,
                              void* d_out, int out_size) {
    const float* x           = (const float*)d_in[0];
    const float* lat         = (const float*)d_in[1];
    const float* k_in_mix    = (const float*)d_in[2];
    const float* k_mid_mix   = (const float*)d_in[3];
    const float* k_out_mix   = (const float*)d_in[4];
    const float* k_short_mix = (const float*)d_in[5];
    const float* b_in_mix    = (const float*)d_in[6];
    const float* b_mid_mix   = (const float*)d_in[7];
    const float* b_out_mix   = (const float*)d_in[8];
    const float* b_short_mix = (const float*)d_in[9];
    const float* w_dyna      = (const float*)d_in[10];
    const float* b_dyna      = (const float*)d_in[11];
    float* out = (float*)d_out;

    cudaFuncSetAttribute(gemm_stage<1>, cudaFuncAttributeMaxDynamicSharedMemorySize, SMEM_G);
    cudaFuncSetAttribute(gemm_stage<2>, cudaFuncAttributeMaxDynamicSharedMemorySize, SMEM_G);
    cudaFuncSetAttribute(gemm_stage<3>, cudaFuncAttributeMaxDynamicSharedMemorySize, SMEM_G3);

    mix_kernel<<<1, 128>>>(lat, w_dyna, b_dyna);
    prep_kernel<<<1537, 256>>>(k_in_mix, k_mid_mix, k_out_mix, k_short_mix,
                               b_in_mix, b_mid_mix, b_out_mix, b_short_mix);
    xt_kernel<<<dim3(128, 8, 16), dim3(32, 8)>>>(x);
    gemm_stage<1><<<dim3(32, 2, 16), 256, SMEM_G>>>(out);
    gemm_stage<2><<<dim3(32, 2, 16), 256, SMEM_G>>>(out);
    gemm_stage<3><<<dim3(32, 2, 16), 256, SMEM_G3>>>(out);
}

// round 10
// speedup vs baseline: 2.5067x; 1.0863x over previous
#include <cuda_runtime.h>
#include <cuda_fp16.h>
#include <cstdint>

// ============================================================================
// MixResidualBlockC via warp-level fp16 mma.sync (pure fp16 inputs, fp32 acc):
//   stage1: h1 = sincos(W1[256,256] @ xt)           (pixel-major fp16)
//   stage2: h2 = sincos(W2[256,512] @ h1)
//   stage3: out = W3[256,768] @ [h2 ; xt] + b3      (W3 = [k_out | k_short])
// R10: CTA 128x128, 4 warps (2x2), warp tile 64x64, BK=64 (144B rows),
// 2 CTAs/SM.  wf/MMA 1.5 -> 1.0, syncs/CTA quartered.
// ============================================================================

#define NPIX 4096
#define NB 16
#define STRIDE 144                     // bytes per 64-fp16 smem row (padded)
#define PLANE (128 * STRIDE)           // 18432 B per plane tile
#define BUFSZ (2 * PLANE)              // A | B = 36864 B
#define SMEM_G 73728                   // 2 buffers; also covers MODE3 transpose

// -------------------- device scratch --------------------------------------
__device__ float g_mix[NB * 8];
__device__ float g_b1[NB * 256], g_b2[NB * 256], g_b3[NB * 256];
__device__ __half g_w1[NB * 256 * 256];
__device__ __half g_w2[NB * 256 * 512];
__device__ __half g_w3[NB * 256 * 768];
__device__ __half g_xt[(size_t)NB * NPIX * 256];
__device__ __half g_h1[(size_t)NB * NPIX * 512];
__device__ __half g_h2[(size_t)NB * NPIX * 512];

// -------------------- PTX helpers (all arch-portable) ----------------------
__device__ __forceinline__ uint32_t smem_u32(const void* p) {
    uint32_t a;
    asm("{ .reg .u64 t; cvta.to.shared.u64 t, %1; cvt.u32.u64 %0, t; }" : "=r"(a) : "l"(p));
    return a;
}
__device__ __forceinline__ void cpa16(uint32_t dst, const void* src) {
    asm volatile("cp.async.cg.shared.global [%0], [%1], 16;" :: "r"(dst), "l"(src));
}
__device__ __forceinline__ void cpa_commit() { asm volatile("cp.async.commit_group;"); }

__device__ __forceinline__ void ldsm_x4(uint32_t* r, uint32_t addr) {
    asm volatile("ldmatrix.sync.aligned.m8n8.x4.shared.b16 {%0,%1,%2,%3}, [%4];"
                 : "=r"(r[0]), "=r"(r[1]), "=r"(r[2]), "=r"(r[3]) : "r"(addr));
}
__device__ __forceinline__ void mma_f16(float* d, const uint32_t* a,
                                        uint32_t b0, uint32_t b1) {
    asm volatile(
        "mma.sync.aligned.m16n8k16.row.col.f32.f16.f16.f32 "
        "{%0,%1,%2,%3}, {%4,%5,%6,%7}, {%8,%9}, {%0,%1,%2,%3};"
        : "+f"(d[0]), "+f"(d[1]), "+f"(d[2]), "+f"(d[3])
        : "r"(a[0]), "r"(a[1]), "r"(a[2]), "r"(a[3]), "r"(b0), "r"(b1));
}
__device__ __forceinline__ uint32_t packh2(float a, float b) {
    __half h0 = __float2half_rn(a), h1 = __float2half_rn(b);
    return (uint32_t)__half_as_ushort(h0) | ((uint32_t)__half_as_ushort(h1) << 16);
}

// -------------------- K0: mixing coefficients ------------------------------
__global__ void mix_kernel(const float* __restrict__ lat, const float* __restrict__ wd,
                           const float* __restrict__ bd) {
    int t = threadIdx.x;
    if (t < 128) {
        int b = t >> 3, m = t & 7;
        float a = bd[m];
        const float* lp = lat + b * 512;
        const float* wp = wd + m * 512;
        #pragma unroll 8
        for (int l = 0; l < 512; l++) a += lp[l] * wp[l];
        g_mix[t] = a;
    }
}

// -------------------- K1: weight mixing -> fp16 ----------------------------
__global__ void prep_kernel(const float* __restrict__ kin, const float* __restrict__ kmid,
                            const float* __restrict__ kout, const float* __restrict__ ksh,
                            const float* __restrict__ bin, const float* __restrict__ bmid,
                            const float* __restrict__ bout, const float* __restrict__ bsh) {
    __shared__ float smix[128];
    if (threadIdx.x < 128) smix[threadIdx.x] = g_mix[threadIdx.x];
    __syncthreads();
    int p = blockIdx.x * 256 + threadIdx.x;
    float v[8];

    if (p < 65536) {  // w1 (k_in)
        #pragma unroll
        for (int m = 0; m < 8; m++) v[m] = kin[m * 65536 + p];
        #pragma unroll
        for (int b = 0; b < NB; b++) {
            float a = 0.f;
            #pragma unroll
            for (int m = 0; m < 8; m++) a += smix[b * 8 + m] * v[m];
            g_w1[b * 65536 + p] = __float2half_rn(a);
        }
    } else if (p < 196608) {  // w2 (k_mid)
        int q = p - 65536;
        #pragma unroll
        for (int m = 0; m < 8; m++) v[m] = kmid[m * 131072 + q];
        #pragma unroll
        for (int b = 0; b < NB; b++) {
            float a = 0.f;
            #pragma unroll
            for (int m = 0; m < 8; m++) a += smix[b * 8 + m] * v[m];
            g_w2[b * 131072 + q] = __float2half_rn(a);
        }
    } else if (p < 327680) {  // w3 k_out part: cols [0,512)
        int q = p - 196608;
        int o = q >> 9, i = q & 511;
        #pragma unroll
        for (int m = 0; m < 8; m++) v[m] = kout[m * 131072 + q];
        int di = o * 768 + i;
        #pragma unroll
        for (int b = 0; b < NB; b++) {
            float a = 0.f;
            #pragma unroll
            for (int m = 0; m < 8; m++) a += smix[b * 8 + m] * v[m];
            g_w3[b * 196608 + di] = __float2half_rn(a);
        }
    } else if (p < 393216) {  // w3 k_short part: cols [512,768)
        int q = p - 327680;
        int o = q >> 8, i = q & 255;
        #pragma unroll
        for (int m = 0; m < 8; m++) v[m] = ksh[m * 65536 + q];
        int di = o * 768 + 512 + i;
        #pragma unroll
        for (int b = 0; b < NB; b++) {
            float a = 0.f;
            #pragma unroll
            for (int m = 0; m < 8; m++) a += smix[b * 8 + m] * v[m];
            g_w3[b * 196608 + di] = __float2half_rn(a);
        }
    } else if (p < 393472) {  // biases
        int r = p - 393216;
        float vi[8], vm[8], vo[8];
        #pragma unroll
        for (int m = 0; m < 8; m++) {
            vi[m] = bin[m * 256 + r];
            vm[m] = bmid[m * 256 + r];
            vo[m] = bout[m * 256 + r] + bsh[m * 256 + r];
        }
        #pragma unroll
        for (int b = 0; b < NB; b++) {
            float a1 = 0.f, a2 = 0.f, a3 = 0.f;
            #pragma unroll
            for (int m = 0; m < 8; m++) {
                float mx = smix[b * 8 + m];
                a1 += mx * vi[m]; a2 += mx * vm[m]; a3 += mx * vo[m];
            }
            g_b1[b * 256 + r] = a1;
            g_b2[b * 256 + r] = a2;
            g_b3[b * 256 + r] = a3;
        }
    }
}

// -------------------- K2: x transpose  x[b,c,p] -> xt[b,p,c] (fp16) --------
__global__ void xt_kernel(const float* __restrict__ x) {
    __shared__ float ts[32][33];
    int b = blockIdx.z, p0 = blockIdx.x * 32, c0 = blockIdx.y * 32;
    const float* src = x + ((size_t)b * 256 + c0) * NPIX + p0;
    for (int r = threadIdx.y; r < 32; r += 8)
        ts[r][threadIdx.x] = src[(size_t)r * NPIX + threadIdx.x];
    __syncthreads();
    int lane = threadIdx.x;
    for (int pr = threadIdx.y; pr < 32; pr += 8) {
        size_t di = ((size_t)b * NPIX + p0 + pr) * 256 + c0 + lane;
        g_xt[di] = __float2half_rn(ts[lane][pr]);
    }
}

// -------------------- GEMM stage (pure fp16 mma.sync) ----------------------
// CTA 128x128, 4 warps (2x2), warp tile 64x64, BK=64.
template <int MODE>  // 1,2,3
__global__ void __launch_bounds__(128, 2)
gemm_stage(float* __restrict__ out) {
    constexpr int K = (MODE == 1) ? 256 : (MODE == 2) ? 512 : 768;
    constexpr int NCH = K / 64;
    constexpr int AROW = (MODE == 1) ? 256 : 512;

    extern __shared__ __align__(16) char dsm[];
    const uint32_t sbase = smem_u32(dsm);
    __shared__ float sbias[128];

    const int tid = threadIdx.x;
    const int lane = tid & 31;
    const int wid = tid >> 5;
    const int warp_m = wid & 1;       // 0..1  (64 px each)
    const int warp_n = wid >> 1;      // 0..1  (64 ch each)
    const int b = blockIdx.z;
    const int p0 = blockIdx.x * 128;
    const int cg0 = blockIdx.y * 128;

    const __half *A, *B;
    const float* bias;
    if constexpr (MODE == 1) {
        A = g_xt + (size_t)b * NPIX * 256;
        B = g_w1 + (size_t)b * 65536;
        bias = g_b1 + b * 256;
    } else if constexpr (MODE == 2) {
        A = g_h1 + (size_t)b * NPIX * 512;
        B = g_w2 + (size_t)b * 131072;
        bias = g_b2 + b * 256;
    } else {
        A = g_h2 + (size_t)b * NPIX * 512;
        B = g_w3 + (size_t)b * 196608;
        bias = g_b3 + b * 256;
    }
    const __half* Xt = g_xt + (size_t)b * NPIX * 256;  // MODE3 tail

    if (tid < 128) sbias[tid] = bias[cg0 + tid];

    // ---- chunk copier: 2048 x 16B (A | B planes, 128 rows x 8 units) ------
    auto copy_chunk = [&](int ch, int buf) {
        const int k0 = ch * 64;
        const uint32_t bb = sbase + buf * BUFSZ;
        const __half* pA = A;
        int acol = k0, arow = AROW;
        if (MODE == 3 && k0 >= 512) { pA = Xt; acol = k0 - 512; arow = 256; }
        #pragma unroll
        for (int j = 0; j < 16; j++) {
            int u = tid + j * 128;
            int plane = u >> 10;          // 0 A, 1 B
            int r = (u >> 3) & 127;
            int c = u & 7;
            uint32_t dst = bb + plane * PLANE + r * STRIDE + c * 16;
            const __half* src;
            if (plane == 0) src = pA + (size_t)(p0 + r) * arow + acol + c * 8;
            else            src = B + (size_t)(cg0 + r) * K + k0 + c * 8;
            cpa16(dst, src);
        }
        cpa_commit();
    };

    // ---- ldmatrix lane address offsets ----
    const int a_row_off = (warp_m * 64 + (lane & 15)) * STRIDE + ((lane >> 4) & 1) * 16;
    const int b_row_off = (warp_n * 64 + (lane & 15)) * STRIDE + ((lane >> 4) & 1) * 16;

    float acc[4][8][4];
    #pragma unroll
    for (int i = 0; i < 4; i++)
        #pragma unroll
        for (int j = 0; j < 8; j++)
            #pragma unroll
            for (int q = 0; q < 4; q++) acc[i][j][q] = 0.f;

    copy_chunk(0, 0);
    if (NCH > 1) copy_chunk(1, 1);

    for (int it = 0; it < NCH; it++) {
        const int buf = it & 1;
        if (it + 1 < NCH) asm volatile("cp.async.wait_group 1;" ::: "memory");
        else              asm volatile("cp.async.wait_group 0;" ::: "memory");
        __syncthreads();
        const uint32_t bb = sbase + buf * BUFSZ;

        #pragma unroll
        for (int ks = 0; ks < 4; ks++) {
            uint32_t fA[4][4], fB[4][4];
            #pragma unroll
            for (int mi = 0; mi < 4; mi++)
                ldsm_x4(fA[mi], bb + a_row_off + mi * (16 * STRIDE) + ks * 32);
            #pragma unroll
            for (int np = 0; np < 4; np++)
                ldsm_x4(fB[np], bb + PLANE + b_row_off + np * (16 * STRIDE) + ks * 32);
            #pragma unroll
            for (int mi = 0; mi < 4; mi++)
                #pragma unroll
                for (int np = 0; np < 4; np++) {
                    mma_f16(acc[mi][np * 2 + 0], fA[mi], fB[np][0], fB[np][2]);
                    mma_f16(acc[mi][np * 2 + 1], fA[mi], fB[np][1], fB[np][3]);
                }
        }
        if (it + 2 < NCH) {
            __syncthreads();           // all warps done reading buf
            copy_chunk(it + 2, buf);
        }
    }

    // ---- epilogue -----------------------------------------------------------
    const int lg = lane >> 2;          // row-in-group 0..7
    const int l2 = (lane & 3) * 2;     // col pair

    if constexpr (MODE != 3) {
        __half* H = (MODE == 1) ? g_h1 : g_h2;
        #pragma unroll
        for (int mi = 0; mi < 4; mi++) {
            const int pix = p0 + warp_m * 64 + mi * 16 + lg;
            const size_t r0 = ((size_t)b * NPIX + pix) * 512;
            const size_t r1 = r0 + 8 * 512;
            #pragma unroll
            for (int ni = 0; ni < 8; ni++) {
                const int chl = warp_n * 64 + ni * 8 + l2;   // local 0..127
                const int chg = cg0 + chl;                   // global 0..255
                const float b0 = sbias[chl], b1 = sbias[chl + 1];
                #pragma unroll
                for (int h = 0; h < 2; h++) {
                    const size_t row = h ? r1 : r0;
                    float v0 = acc[mi][ni][h * 2 + 0] + b0;
                    float v1 = acc[mi][ni][h * 2 + 1] + b1;
                    float s0, c0, s1, c1;
                    __sincosf(v0, &s0, &c0);
                    __sincosf(v1, &s1, &c1);
                    *(uint32_t*)(H + row + chg)       = packh2(s0, s1);
                    *(uint32_t*)(H + row + chg + 256) = packh2(c0, c1);
                }
            }
        }
    } else {
        // stage smem [128 px][132] fp32 then coalesced channel-major writes
        float* smf = (float*)dsm;
        __syncthreads();
        #pragma unroll
        for (int mi = 0; mi < 4; mi++) {
            const int pxl0 = warp_m * 64 + mi * 16 + lg;
            #pragma unroll
            for (int ni = 0; ni < 8; ni++) {
                const int chl = warp_n * 64 + ni * 8 + l2;
                const float b0 = sbias[chl], b1 = sbias[chl + 1];
                smf[pxl0 * 132 + chl]           = acc[mi][ni][0] + b0;
                smf[pxl0 * 132 + chl + 1]       = acc[mi][ni][1] + b1;
                smf[(pxl0 + 8) * 132 + chl]     = acc[mi][ni][2] + b0;
                smf[(pxl0 + 8) * 132 + chl + 1] = acc[mi][ni][3] + b1;
            }
        }
        __syncthreads();
        const int ch = tid;                // 0..127
        float* orow = out + ((size_t)b * 256 + cg0 + ch) * NPIX + p0;
        #pragma unroll
        for (int g = 0; g < 32; g++) {
            float4 v;
            v.x = smf[(g * 4 + 0) * 132 + ch];
            v.y = smf[(g * 4 + 1) * 132 + ch];
            v.z = smf[(g * 4 + 2) * 132 + ch];
            v.w = smf[(g * 4 + 3) * 132 + ch];
            *(float4*)(orow + g * 4) = v;
        }
    }
}

// -------------------- launch ------------------------------------------------
extern "C" void kernel_launch(void* const* d_in, const int* in_sizes, int n_in,
                              void* d_out, int out_size) {
    const float* x           = (const float*)d_in[0];
    const float* lat         = (const float*)d_in[1];
    const float* k_in_mix    = (const float*)d_in[2];
    const float* k_mid_mix   = (const float*)d_in[3];
    const float* k_out_mix   = (const float*)d_in[4];
    const float* k_short_mix = (const float*)d_in[5];
    const float* b_in_mix    = (const float*)d_in[6];
    const float* b_mid_mix   = (const float*)d_in[7];
    const float* b_out_mix   = (const float*)d_in[8];
    const float* b_short_mix = (const float*)d_in[9];
    const float* w_dyna      = (const float*)d_in[10];
    const float* b_dyna      = (const float*)d_in[11];
    float* out = (float*)d_out;

    cudaFuncSetAttribute(gemm_stage<1>, cudaFuncAttributeMaxDynamicSharedMemorySize, SMEM_G);
    cudaFuncSetAttribute(gemm_stage<2>, cudaFuncAttributeMaxDynamicSharedMemorySize, SMEM_G);
    cudaFuncSetAttribute(gemm_stage<3>, cudaFuncAttributeMaxDynamicSharedMemorySize, SMEM_G);

    mix_kernel<<<1, 128>>>(lat, w_dyna, b_dyna);
    prep_kernel<<<1537, 256>>>(k_in_mix, k_mid_mix, k_out_mix, k_short_mix,
                               b_in_mix, b_mid_mix, b_out_mix, b_short_mix);
    xt_kernel<<<dim3(128, 8, 16), dim3(32, 8)>>>(x);
    gemm_stage<1><<<dim3(32, 2, 16), 128, SMEM_G>>>(out);
    gemm_stage<2><<<dim3(32, 2, 16), 128, SMEM_G>>>(out);
    gemm_stage<3><<<dim3(32, 2, 16), 128, SMEM_G>>>(out);
}